// round 6
// baseline (speedup 1.0000x reference)
#include <cuda_runtime.h>
#include <cstdint>

// ---------------- problem dims ----------------
#define BB 8
#define NN 4096
#define DD 2048
#define NBLK 16
#define DB 128
#define PP 512
#define HH 512            // MLP hidden = 4*DB
#define NROWS (PP*NBLK)   // 8192 rows through the MLP
#define QROWS (BB*NN)     // 32768 query rows
#define EPS 1e-5f
#define INV_SQRT_DB 0.08838834764831845f

static_assert(NROWS % 64 == 0 && HH % 64 == 0 && DB % 64 == 0, "tile divisibility");
static_assert(QROWS % 64 == 0, "q tile divisibility");

// ---------------- scratch (device globals; no runtime alloc) ----------------
__device__ float g_h1[NROWS * HH];          // 16 MB
__device__ float g_h2[NROWS * HH];          // 16 MB
__device__ float g_mem[NROWS * DB];         // 4 MB
__device__ float g_memn[NBLK * PP * DB];    // 4 MB, layout [h][p][d]

// ---------------- helpers ----------------
__device__ __forceinline__ float tf32r(float x) {
    uint32_t u;
    asm("cvt.rna.tf32.f32 %0, %1;" : "=r"(u) : "f"(x));
    return __uint_as_float(u);
}
__device__ __forceinline__ uint32_t F2U(float x) { return __float_as_uint(x); }

__device__ __forceinline__ void mma_tf32(float& d0, float& d1, float& d2, float& d3,
                                         uint32_t a0, uint32_t a1, uint32_t a2, uint32_t a3,
                                         uint32_t b0, uint32_t b1) {
    asm volatile(
        "mma.sync.aligned.m16n8k8.row.col.f32.tf32.tf32.f32 "
        "{%0,%1,%2,%3}, {%4,%5,%6,%7}, {%8,%9}, {%0,%1,%2,%3};\n"
        : "+f"(d0), "+f"(d1), "+f"(d2), "+f"(d3)
        : "r"(a0), "r"(a1), "r"(a2), "r"(a3), "r"(b0), "r"(b1));
}

// ============================================================================
// GEMM: C[M,N] = act(A[M,K] @ W[N,K]^T + bias), compensated tf32 (3 MMAs)
// block tile 64x64, 256 threads, 8 warps each 16x32
// ============================================================================
#define KC 32
__global__ void __launch_bounds__(256, 2)
gemm_tf32c(const float* __restrict__ A, const float* __restrict__ W,
           const float* __restrict__ bias, float* __restrict__ C,
           int M, int N, int K, int relu) {
    __shared__ float Ah[64][KC + 4], Al[64][KC + 4];
    __shared__ float Bh[64][KC + 4], Bl[64][KC + 4];

    const int m0 = blockIdx.y * 64;
    const int n0 = blockIdx.x * 64;
    const int t = threadIdx.x;
    const int lane = t & 31;
    const int w = t >> 5;
    const int wm = w >> 1;   // 0..3  (m quarters of 16)
    const int wn = w & 1;    // 0..1  (n halves of 32)

    float acc[4][4];
#pragma unroll
    for (int f = 0; f < 4; f++)
#pragma unroll
        for (int i = 0; i < 4; i++) acc[f][i] = 0.f;

    for (int k0 = 0; k0 < K; k0 += KC) {
        __syncthreads();
        for (int i = t; i < 64 * KC; i += 256) {
            int r = i / KC, c = i % KC;
            float va = A[(size_t)(m0 + r) * K + k0 + c];
            float vb = W[(size_t)(n0 + r) * K + k0 + c];
            float vah = tf32r(va), vbh = tf32r(vb);
            Ah[r][c] = vah;  Al[r][c] = tf32r(va - vah);
            Bh[r][c] = vbh;  Bl[r][c] = tf32r(vb - vbh);
        }
        __syncthreads();
#pragma unroll
        for (int ks = 0; ks < KC; ks += 8) {
            const int ar = wm * 16 + (lane >> 2);
            const int ac = ks + (lane & 3);
            uint32_t a0h = F2U(Ah[ar][ac]),     a1h = F2U(Ah[ar + 8][ac]);
            uint32_t a2h = F2U(Ah[ar][ac + 4]), a3h = F2U(Ah[ar + 8][ac + 4]);
            uint32_t a0l = F2U(Al[ar][ac]),     a1l = F2U(Al[ar + 8][ac]);
            uint32_t a2l = F2U(Al[ar][ac + 4]), a3l = F2U(Al[ar + 8][ac + 4]);
#pragma unroll
            for (int f = 0; f < 4; f++) {
                const int bn = wn * 32 + f * 8 + (lane >> 2);
                const int bk = ks + (lane & 3);
                uint32_t b0h = F2U(Bh[bn][bk]), b1h = F2U(Bh[bn][bk + 4]);
                uint32_t b0l = F2U(Bl[bn][bk]), b1l = F2U(Bl[bn][bk + 4]);
                mma_tf32(acc[f][0], acc[f][1], acc[f][2], acc[f][3],
                         a0h, a1h, a2h, a3h, b0h, b1h);
                mma_tf32(acc[f][0], acc[f][1], acc[f][2], acc[f][3],
                         a0h, a1h, a2h, a3h, b0l, b1l);
                mma_tf32(acc[f][0], acc[f][1], acc[f][2], acc[f][3],
                         a0l, a1l, a2l, a3l, b0h, b1h);
            }
        }
    }
    // epilogue
    const int row = m0 + wm * 16 + (lane >> 2);
#pragma unroll
    for (int f = 0; f < 4; f++) {
        const int col = n0 + wn * 32 + f * 8 + (lane & 3) * 2;
        float bv0 = bias[col], bv1 = bias[col + 1];
        float v0 = acc[f][0] + bv0, v1 = acc[f][1] + bv1;
        float v2 = acc[f][2] + bv0, v3 = acc[f][3] + bv1;
        if (relu) {
            v0 = fmaxf(v0, 0.f); v1 = fmaxf(v1, 0.f);
            v2 = fmaxf(v2, 0.f); v3 = fmaxf(v3, 0.f);
        }
        C[(size_t)row * N + col] = v0;       C[(size_t)row * N + col + 1] = v1;
        C[(size_t)(row + 8) * N + col] = v2; C[(size_t)(row + 8) * N + col + 1] = v3;
    }
}

// ============================================================================
// Block-LN of mem rows, scatter into [h][p][d] layout
// one warp per row of 128
// ============================================================================
__global__ void __launch_bounds__(256, 4)
mem_ln_kernel(const float* __restrict__ mem, float* __restrict__ memn) {
    const int rr = blockIdx.x * 8 + (threadIdx.x >> 5);
    const int lane = threadIdx.x & 31;
    float4 v = *(const float4*)(mem + (size_t)rr * DB + lane * 4);
    float s = v.x + v.y + v.z + v.w;
    float ss = v.x * v.x + v.y * v.y + v.z * v.z + v.w * v.w;
#pragma unroll
    for (int o = 16; o; o >>= 1) {
        s  += __shfl_xor_sync(0xffffffffu, s, o);
        ss += __shfl_xor_sync(0xffffffffu, ss, o);
    }
    float mu = s * (1.f / DB);
    float var = ss * (1.f / DB) - mu * mu;
    float rs = rsqrtf(var + EPS);
    const int p = rr >> 4, h = rr & 15;
    float* o = memn + ((size_t)h * PP + p) * DB + lane * 4;
    o[0] = (v.x - mu) * rs; o[1] = (v.y - mu) * rs;
    o[2] = (v.z - mu) * rs; o[3] = (v.w - mu) * rs;
}

// ============================================================================
// Fused attention: per (q-tile of 64, head): LN(q) -> S = QK^T -> softmax ->
// O = P K. K streamed from g_memn[h] (4 MB, L2-resident). Full scores in smem.
// 256 threads, ~195KB dynamic smem.
// ============================================================================
#define QS_STRIDE 132
#define SC_STRIDE 516
__global__ void __launch_bounds__(256, 1)
attn_kernel(const float* __restrict__ Q, const float* __restrict__ Kmem,
            float* __restrict__ O) {
    extern __shared__ float sm[];
    float* qs = sm;                         // [64][132]
    float* ks = sm + 64 * QS_STRIDE;        // [64][132]
    float* sc = sm + 2 * 64 * QS_STRIDE;    // [64][516]

    const int h = blockIdx.y;
    const int q0 = blockIdx.x * 64;
    const int t = threadIdx.x;
    const int lane = t & 31;
    const int w = t >> 5;

    // ---- stage 1: block-LN of q rows (+ DB^-1/2 scale), tf32-rounded ----
    for (int rr = w; rr < 64; rr += 8) {
        const float4 v = *(const float4*)(Q + (size_t)(q0 + rr) * DD + h * DB + lane * 4);
        float s = v.x + v.y + v.z + v.w;
        float ss = v.x * v.x + v.y * v.y + v.z * v.z + v.w * v.w;
#pragma unroll
        for (int o = 16; o; o >>= 1) {
            s  += __shfl_xor_sync(0xffffffffu, s, o);
            ss += __shfl_xor_sync(0xffffffffu, ss, o);
        }
        float mu = s * (1.f / DB);
        float var = ss * (1.f / DB) - mu * mu;
        float scl = rsqrtf(var + EPS) * INV_SQRT_DB;
        float* qr = qs + rr * QS_STRIDE + lane * 4;
        qr[0] = tf32r((v.x - mu) * scl); qr[1] = tf32r((v.y - mu) * scl);
        qr[2] = tf32r((v.z - mu) * scl); qr[3] = tf32r((v.w - mu) * scl);
    }

    const float* KH = Kmem + (size_t)h * PP * DB;

    // ---- stage 2: scores S[64][512] ----
    {
        const int wm = w >> 1, wn = w & 1;
        for (int pt = 0; pt < 8; pt++) {
            __syncthreads();
            for (int i = t; i < 64 * DB; i += 256) {
                int r = i >> 7, c = i & 127;
                ks[r * QS_STRIDE + c] = tf32r(KH[(size_t)(pt * 64 + r) * DB + c]);
            }
            __syncthreads();
            float acc[4][4];
#pragma unroll
            for (int f = 0; f < 4; f++)
#pragma unroll
                for (int i = 0; i < 4; i++) acc[f][i] = 0.f;
#pragma unroll
            for (int k = 0; k < DB; k += 8) {
                const int ar = wm * 16 + (lane >> 2);
                const int ac = k + (lane & 3);
                uint32_t a0 = F2U(qs[ar * QS_STRIDE + ac]);
                uint32_t a1 = F2U(qs[(ar + 8) * QS_STRIDE + ac]);
                uint32_t a2 = F2U(qs[ar * QS_STRIDE + ac + 4]);
                uint32_t a3 = F2U(qs[(ar + 8) * QS_STRIDE + ac + 4]);
#pragma unroll
                for (int f = 0; f < 4; f++) {
                    const int bp = wn * 32 + f * 8 + (lane >> 2);
                    uint32_t b0 = F2U(ks[bp * QS_STRIDE + k + (lane & 3)]);
                    uint32_t b1 = F2U(ks[bp * QS_STRIDE + k + 4 + (lane & 3)]);
                    mma_tf32(acc[f][0], acc[f][1], acc[f][2], acc[f][3],
                             a0, a1, a2, a3, b0, b1);
                }
            }
            const int row = wm * 16 + (lane >> 2);
#pragma unroll
            for (int f = 0; f < 4; f++) {
                const int col = pt * 64 + wn * 32 + f * 8 + (lane & 3) * 2;
                sc[row * SC_STRIDE + col] = acc[f][0];
                sc[row * SC_STRIDE + col + 1] = acc[f][1];
                sc[(row + 8) * SC_STRIDE + col] = acc[f][2];
                sc[(row + 8) * SC_STRIDE + col + 1] = acc[f][3];
            }
        }
    }
    __syncthreads();

    // ---- stage 3: softmax over 512, result tf32-rounded back into sc ----
    for (int rr = w; rr < 64; rr += 8) {
        float vals[16];
        float m = -1e30f;
#pragma unroll
        for (int i = 0; i < 16; i++) {
            vals[i] = sc[rr * SC_STRIDE + lane + i * 32];
            m = fmaxf(m, vals[i]);
        }
#pragma unroll
        for (int o = 16; o; o >>= 1) m = fmaxf(m, __shfl_xor_sync(0xffffffffu, m, o));
        float s = 0.f;
#pragma unroll
        for (int i = 0; i < 16; i++) { vals[i] = __expf(vals[i] - m); s += vals[i]; }
#pragma unroll
        for (int o = 16; o; o >>= 1) s += __shfl_xor_sync(0xffffffffu, s, o);
        float inv = 1.f / s;
#pragma unroll
        for (int i = 0; i < 16; i++)
            sc[rr * SC_STRIDE + lane + i * 32] = tf32r(vals[i] * inv);
    }

    // ---- stage 4: O[64][128] = P[64][512] @ K[512][128] ----
    {
        const int wm = w >> 1, wn = w & 1;
        float acc[8][4];
#pragma unroll
        for (int f = 0; f < 8; f++)
#pragma unroll
            for (int i = 0; i < 4; i++) acc[f][i] = 0.f;

        for (int pt = 0; pt < 8; pt++) {
            __syncthreads();
            for (int i = t; i < 64 * DB; i += 256) {
                int r = i >> 7, c = i & 127;
                ks[r * QS_STRIDE + c] = tf32r(KH[(size_t)(pt * 64 + r) * DB + c]);
            }
            __syncthreads();
#pragma unroll
            for (int k8 = 0; k8 < 64; k8 += 8) {
                const int ar = wm * 16 + (lane >> 2);
                const int ac = pt * 64 + k8 + (lane & 3);
                uint32_t a0 = F2U(sc[ar * SC_STRIDE + ac]);
                uint32_t a1 = F2U(sc[(ar + 8) * SC_STRIDE + ac]);
                uint32_t a2 = F2U(sc[ar * SC_STRIDE + ac + 4]);
                uint32_t a3 = F2U(sc[(ar + 8) * SC_STRIDE + ac + 4]);
#pragma unroll
                for (int f = 0; f < 8; f++) {
                    const int bn = wn * 64 + f * 8 + (lane >> 2);
                    const int bk = k8 + (lane & 3);
                    uint32_t b0 = F2U(ks[bk * QS_STRIDE + bn]);
                    uint32_t b1 = F2U(ks[(bk + 4) * QS_STRIDE + bn]);
                    mma_tf32(acc[f][0], acc[f][1], acc[f][2], acc[f][3],
                             a0, a1, a2, a3, b0, b1);
                }
            }
        }
        const int row = q0 + wm * 16 + (lane >> 2);
#pragma unroll
        for (int f = 0; f < 8; f++) {
            const int col = h * DB + wn * 64 + f * 8 + (lane & 3) * 2;
            size_t base = (size_t)row * DD + col;
            O[base] = acc[f][0];
            O[base + 1] = acc[f][1];
            O[base + (size_t)8 * DD] = acc[f][2];
            O[base + (size_t)8 * DD + 1] = acc[f][3];
        }
    }
}

// ============================================================================
// launch
// ============================================================================
extern "C" void kernel_launch(void* const* d_in, const int* in_sizes, int n_in,
                              void* d_out, int out_size) {
    (void)in_sizes; (void)n_in; (void)out_size;
    const float* q    = (const float*)d_in[0];
    const float* memp = (const float*)d_in[1];
    const float* w1 = (const float*)d_in[2]; const float* b1 = (const float*)d_in[3];
    const float* w2 = (const float*)d_in[4]; const float* b2 = (const float*)d_in[5];
    const float* w3 = (const float*)d_in[6]; const float* b3 = (const float*)d_in[7];
    const float* w4 = (const float*)d_in[8]; const float* b4 = (const float*)d_in[9];
    float* out = (float*)d_out;

    void *p_h1, *p_h2, *p_mem, *p_memn;
    cudaGetSymbolAddress(&p_h1, g_h1);
    cudaGetSymbolAddress(&p_h2, g_h2);
    cudaGetSymbolAddress(&p_mem, g_mem);
    cudaGetSymbolAddress(&p_memn, g_memn);
    float* h1f  = (float*)p_h1;
    float* h2f  = (float*)p_h2;
    float* memf = (float*)p_mem;
    float* memnf = (float*)p_memn;

    // mem MLP (compensated tf32)
    gemm_tf32c<<<dim3(HH / 64, NROWS / 64), 256>>>(memp, w1, b1, h1f, NROWS, HH, DB, 1);
    gemm_tf32c<<<dim3(HH / 64, NROWS / 64), 256>>>(h1f,  w2, b2, h2f, NROWS, HH, HH, 1);
    gemm_tf32c<<<dim3(HH / 64, NROWS / 64), 256>>>(h2f,  w3, b3, h1f, NROWS, HH, HH, 1);
    gemm_tf32c<<<dim3(DB / 64, NROWS / 64), 256>>>(h1f,  w4, b4, memf, NROWS, DB, HH, 0);

    // block-LN of mem -> [h][p][d]
    mem_ln_kernel<<<NROWS / 8, 256>>>(memf, memnf);

    // fused LN + attention
    const int smem_bytes = (2 * 64 * QS_STRIDE + 64 * SC_STRIDE) * sizeof(float);
    cudaFuncSetAttribute(attn_kernel, cudaFuncAttributeMaxDynamicSharedMemorySize, smem_bytes);
    attn_kernel<<<dim3(QROWS / 64, NBLK), 256, smem_bytes>>>(q, memnf, out);
}

// round 7
// speedup vs baseline: 2.2175x; 2.2175x over previous
#include <cuda_runtime.h>
#include <cstdint>

// ---------------- problem dims ----------------
#define BB 8
#define NN 4096
#define DD 2048
#define NBLK 16
#define DB 128
#define PP 512
#define HH 512            // MLP hidden = 4*DB
#define NROWS (PP*NBLK)   // 8192 rows through the MLP
#define QROWS (BB*NN)     // 32768 query rows
#define EPS 1e-5f
#define INV_SQRT_DB 0.08838834764831845f

static_assert(NROWS % 64 == 0 && HH % 64 == 0 && DB % 64 == 0, "tile divisibility");
static_assert(QROWS % 64 == 0, "q tile divisibility");

// ---------------- scratch (device globals; no runtime alloc) ----------------
__device__ float g_h1[NROWS * HH];          // 16 MB
__device__ float g_h2[NROWS * HH];          // 16 MB
__device__ float g_mem[NROWS * DB];         // 4 MB
__device__ float g_memn[NBLK * PP * DB];    // 4 MB, layout [h][p][d]

// ---------------- helpers ----------------
__device__ __forceinline__ float tf32r(float x) {
    uint32_t u;
    asm("cvt.rna.tf32.f32 %0, %1;" : "=r"(u) : "f"(x));
    return __uint_as_float(u);
}
__device__ __forceinline__ uint32_t F2U(float x) { return __float_as_uint(x); }

__device__ __forceinline__ void mma_tf32(float& d0, float& d1, float& d2, float& d3,
                                         uint32_t a0, uint32_t a1, uint32_t a2, uint32_t a3,
                                         uint32_t b0, uint32_t b1) {
    asm volatile(
        "mma.sync.aligned.m16n8k8.row.col.f32.tf32.tf32.f32 "
        "{%0,%1,%2,%3}, {%4,%5,%6,%7}, {%8,%9}, {%0,%1,%2,%3};\n"
        : "+f"(d0), "+f"(d1), "+f"(d2), "+f"(d3)
        : "r"(a0), "r"(a1), "r"(a2), "r"(a3), "r"(b0), "r"(b1));
}

__device__ __forceinline__ void cp16(uint32_t saddr, const float* g) {
    asm volatile("cp.async.cg.shared.global [%0], [%1], 16;\n" :: "r"(saddr), "l"(g));
}

// ============================================================================
// GEMM: C[M,N] = act(A[M,K] @ W[N,K]^T + bias), compensated tf32 (3 MMAs)
// (unchanged from previous passing round)
// ============================================================================
#define KC 32
__global__ void __launch_bounds__(256, 2)
gemm_tf32c(const float* __restrict__ A, const float* __restrict__ W,
           const float* __restrict__ bias, float* __restrict__ C,
           int M, int N, int K, int relu) {
    __shared__ float Ah[64][KC + 4], Al[64][KC + 4];
    __shared__ float Bh[64][KC + 4], Bl[64][KC + 4];

    const int m0 = blockIdx.y * 64;
    const int n0 = blockIdx.x * 64;
    const int t = threadIdx.x;
    const int lane = t & 31;
    const int w = t >> 5;
    const int wm = w >> 1;
    const int wn = w & 1;

    float acc[4][4];
#pragma unroll
    for (int f = 0; f < 4; f++)
#pragma unroll
        for (int i = 0; i < 4; i++) acc[f][i] = 0.f;

    for (int k0 = 0; k0 < K; k0 += KC) {
        __syncthreads();
        for (int i = t; i < 64 * KC; i += 256) {
            int r = i / KC, c = i % KC;
            float va = A[(size_t)(m0 + r) * K + k0 + c];
            float vb = W[(size_t)(n0 + r) * K + k0 + c];
            float vah = tf32r(va), vbh = tf32r(vb);
            Ah[r][c] = vah;  Al[r][c] = tf32r(va - vah);
            Bh[r][c] = vbh;  Bl[r][c] = tf32r(vb - vbh);
        }
        __syncthreads();
#pragma unroll
        for (int ks = 0; ks < KC; ks += 8) {
            const int ar = wm * 16 + (lane >> 2);
            const int ac = ks + (lane & 3);
            uint32_t a0h = F2U(Ah[ar][ac]),     a1h = F2U(Ah[ar + 8][ac]);
            uint32_t a2h = F2U(Ah[ar][ac + 4]), a3h = F2U(Ah[ar + 8][ac + 4]);
            uint32_t a0l = F2U(Al[ar][ac]),     a1l = F2U(Al[ar + 8][ac]);
            uint32_t a2l = F2U(Al[ar][ac + 4]), a3l = F2U(Al[ar + 8][ac + 4]);
#pragma unroll
            for (int f = 0; f < 4; f++) {
                const int bn = wn * 32 + f * 8 + (lane >> 2);
                const int bk = ks + (lane & 3);
                uint32_t b0h = F2U(Bh[bn][bk]), b1h = F2U(Bh[bn][bk + 4]);
                uint32_t b0l = F2U(Bl[bn][bk]), b1l = F2U(Bl[bn][bk + 4]);
                mma_tf32(acc[f][0], acc[f][1], acc[f][2], acc[f][3],
                         a0h, a1h, a2h, a3h, b0h, b1h);
                mma_tf32(acc[f][0], acc[f][1], acc[f][2], acc[f][3],
                         a0h, a1h, a2h, a3h, b0l, b1l);
                mma_tf32(acc[f][0], acc[f][1], acc[f][2], acc[f][3],
                         a0l, a1l, a2l, a3l, b0h, b1h);
            }
        }
    }
    const int row = m0 + wm * 16 + (lane >> 2);
#pragma unroll
    for (int f = 0; f < 4; f++) {
        const int col = n0 + wn * 32 + f * 8 + (lane & 3) * 2;
        float bv0 = bias[col], bv1 = bias[col + 1];
        float v0 = acc[f][0] + bv0, v1 = acc[f][1] + bv1;
        float v2 = acc[f][2] + bv0, v3 = acc[f][3] + bv1;
        if (relu) {
            v0 = fmaxf(v0, 0.f); v1 = fmaxf(v1, 0.f);
            v2 = fmaxf(v2, 0.f); v3 = fmaxf(v3, 0.f);
        }
        C[(size_t)row * N + col] = v0;       C[(size_t)row * N + col + 1] = v1;
        C[(size_t)(row + 8) * N + col] = v2; C[(size_t)(row + 8) * N + col + 1] = v3;
    }
}

// ============================================================================
// Block-LN of mem rows, scatter into [h][p][d] layout (unchanged)
// ============================================================================
__global__ void __launch_bounds__(256, 4)
mem_ln_kernel(const float* __restrict__ mem, float* __restrict__ memn) {
    const int rr = blockIdx.x * 8 + (threadIdx.x >> 5);
    const int lane = threadIdx.x & 31;
    float4 v = *(const float4*)(mem + (size_t)rr * DB + lane * 4);
    float s = v.x + v.y + v.z + v.w;
    float ss = v.x * v.x + v.y * v.y + v.z * v.z + v.w * v.w;
#pragma unroll
    for (int o = 16; o; o >>= 1) {
        s  += __shfl_xor_sync(0xffffffffu, s, o);
        ss += __shfl_xor_sync(0xffffffffu, ss, o);
    }
    float mu = s * (1.f / DB);
    float var = ss * (1.f / DB) - mu * mu;
    float rs = rsqrtf(var + EPS);
    const int p = rr >> 4, h = rr & 15;
    float* o = memn + ((size_t)h * PP + p) * DB + lane * 4;
    o[0] = (v.x - mu) * rs; o[1] = (v.y - mu) * rs;
    o[2] = (v.z - mu) * rs; o[3] = (v.w - mu) * rs;
}

// ============================================================================
// Flash-style fused attention: per (q-tile 64, head).
// LN(q) -> per-warp online softmax over its 256-prototype slice, K tiles
// streamed ONCE via double-buffered cp.async, probs stay in registers
// (quad-shuffle C-frag -> A-frag), final wn-pair merge via smem.
// 256 threads, 105 KB smem, 2 CTAs/SM.
// ============================================================================
#define TST 140                 // stride (mod 32 == 12): conflict-free for
                                // qs A-frags, S-stage B-frags AND PV B-frags
#define KTILE (64 * TST)

__global__ void __launch_bounds__(256, 2)
attn_flash(const float* __restrict__ Q, const float* __restrict__ Kmem,
           float* __restrict__ O) {
    extern __shared__ float smf[];
    float* qs = smf;                 // [64][TST]
    float* ks = smf + 64 * TST;      // [2][64][TST] (reused as merge scratch)

    const int h = blockIdx.y;
    const int q0 = blockIdx.x * 64;
    const int t = threadIdx.x;
    const int lane = t & 31;
    const int w = t >> 5;
    const int wm = w >> 1, wn = w & 1;
    const int qq = lane & 3;         // quad slot
    const int r4 = lane >> 2;        // row-within-16 / n-within-8

    // ---- q block-LN (+ DB^-1/2), rna->tf32, into qs ----
    for (int rr = w; rr < 64; rr += 8) {
        const float4 v = *(const float4*)(Q + (size_t)(q0 + rr) * DD + h * DB + lane * 4);
        float s = v.x + v.y + v.z + v.w;
        float ss = v.x * v.x + v.y * v.y + v.z * v.z + v.w * v.w;
#pragma unroll
        for (int o = 16; o; o >>= 1) {
            s  += __shfl_xor_sync(0xffffffffu, s, o);
            ss += __shfl_xor_sync(0xffffffffu, ss, o);
        }
        float mu = s * (1.f / DB);
        float var = ss * (1.f / DB) - mu * mu;
        float scl = rsqrtf(var + EPS) * INV_SQRT_DB;
        float* qr = qs + rr * TST + lane * 4;
        qr[0] = tf32r((v.x - mu) * scl); qr[1] = tf32r((v.y - mu) * scl);
        qr[2] = tf32r((v.z - mu) * scl); qr[3] = tf32r((v.w - mu) * scl);
    }

    const float* KH = Kmem + (size_t)h * PP * DB;

    // prefetch K tile 0
    {
        uint32_t sb = (uint32_t)__cvta_generic_to_shared(ks);
#pragma unroll
        for (int j = 0; j < 8; j++) {
            int cid = t + j * 256;
            int r = cid >> 5, c4 = cid & 31;
            cp16(sb + (uint32_t)(r * TST + c4 * 4) * 4, KH + r * DB + c4 * 4);
        }
        asm volatile("cp.async.commit_group;\n");
    }

    float o[16][4];
#pragma unroll
    for (int nt = 0; nt < 16; nt++)
#pragma unroll
        for (int i = 0; i < 4; i++) o[nt][i] = 0.f;
    float m0 = -1e30f, m1 = -1e30f, l0 = 0.f, l1 = 0.f;

    for (int pt = 0; pt < 8; pt++) {
        asm volatile("cp.async.wait_group 0;\n");
        __syncthreads();
        const float* kb = ks + (pt & 1) * KTILE;
        if (pt < 7) {
            uint32_t sb = (uint32_t)__cvta_generic_to_shared(ks + ((pt + 1) & 1) * KTILE);
            const float* src = KH + (size_t)(pt + 1) * 64 * DB;
#pragma unroll
            for (int j = 0; j < 8; j++) {
                int cid = t + j * 256;
                int r = cid >> 5, c4 = cid & 31;
                cp16(sb + (uint32_t)(r * TST + c4 * 4) * 4, src + r * DB + c4 * 4);
            }
            asm volatile("cp.async.commit_group;\n");
        }

        // ---- S = Q @ K^T  (warp tile 16 x 32) ----
        float acc[4][4];
#pragma unroll
        for (int f = 0; f < 4; f++)
#pragma unroll
            for (int i = 0; i < 4; i++) acc[f][i] = 0.f;
        const int ar = wm * 16 + r4;
#pragma unroll
        for (int k = 0; k < DB; k += 8) {
            uint32_t a0 = F2U(qs[ar * TST + k + qq]);
            uint32_t a1 = F2U(qs[(ar + 8) * TST + k + qq]);
            uint32_t a2 = F2U(qs[ar * TST + k + 4 + qq]);
            uint32_t a3 = F2U(qs[(ar + 8) * TST + k + 4 + qq]);
#pragma unroll
            for (int f = 0; f < 4; f++) {
                const int bp = wn * 32 + f * 8 + r4;
                uint32_t b0 = F2U(kb[bp * TST + k + qq]);
                uint32_t b1 = F2U(kb[bp * TST + k + 4 + qq]);
                mma_tf32(acc[f][0], acc[f][1], acc[f][2], acc[f][3],
                         a0, a1, a2, a3, b0, b1);
            }
        }

        // ---- online softmax update (per warp, rows r4 and r4+8) ----
        float tm0 = -1e30f, tm1 = -1e30f;
#pragma unroll
        for (int f = 0; f < 4; f++) {
            tm0 = fmaxf(tm0, fmaxf(acc[f][0], acc[f][1]));
            tm1 = fmaxf(tm1, fmaxf(acc[f][2], acc[f][3]));
        }
        tm0 = fmaxf(tm0, __shfl_xor_sync(0xffffffffu, tm0, 1));
        tm0 = fmaxf(tm0, __shfl_xor_sync(0xffffffffu, tm0, 2));
        tm1 = fmaxf(tm1, __shfl_xor_sync(0xffffffffu, tm1, 1));
        tm1 = fmaxf(tm1, __shfl_xor_sync(0xffffffffu, tm1, 2));
        float mn0 = fmaxf(m0, tm0), mn1 = fmaxf(m1, tm1);
        float sc0 = __expf(m0 - mn0), sc1 = __expf(m1 - mn1);
        m0 = mn0; m1 = mn1;
        l0 *= sc0; l1 *= sc1;
#pragma unroll
        for (int nt = 0; nt < 16; nt++) {
            o[nt][0] *= sc0; o[nt][1] *= sc0;
            o[nt][2] *= sc1; o[nt][3] *= sc1;
        }
#pragma unroll
        for (int f = 0; f < 4; f++) {
            acc[f][0] = __expf(acc[f][0] - mn0);
            acc[f][1] = __expf(acc[f][1] - mn0);
            acc[f][2] = __expf(acc[f][2] - mn1);
            acc[f][3] = __expf(acc[f][3] - mn1);
            l0 += acc[f][0] + acc[f][1];
            l1 += acc[f][2] + acc[f][3];
        }

        // ---- O += P @ K  (probs reg->reg via quad shuffle) ----
        const int s0 = (lane & 28) | (qq >> 1);
        const int s1 = s0 + 2;
#pragma unroll
        for (int f = 0; f < 4; f++) {
            float v00 = __shfl_sync(0xffffffffu, acc[f][0], s0);
            float v01 = __shfl_sync(0xffffffffu, acc[f][1], s0);
            float v10 = __shfl_sync(0xffffffffu, acc[f][0], s1);
            float v11 = __shfl_sync(0xffffffffu, acc[f][1], s1);
            float w00 = __shfl_sync(0xffffffffu, acc[f][2], s0);
            float w01 = __shfl_sync(0xffffffffu, acc[f][3], s0);
            float w10 = __shfl_sync(0xffffffffu, acc[f][2], s1);
            float w11 = __shfl_sync(0xffffffffu, acc[f][3], s1);
            uint32_t a0 = F2U((qq & 1) ? v01 : v00);   // P[r4,    qq  ]
            uint32_t a2 = F2U((qq & 1) ? v11 : v10);   // P[r4,    qq+4]
            uint32_t a1 = F2U((qq & 1) ? w01 : w00);   // P[r4+8,  qq  ]
            uint32_t a3 = F2U((qq & 1) ? w11 : w10);   // P[r4+8,  qq+4]
            const int kr = wn * 32 + f * 8;
#pragma unroll
            for (int nt = 0; nt < 16; nt++) {
                uint32_t b0 = F2U(kb[(kr + qq) * TST + nt * 8 + r4]);
                uint32_t b1 = F2U(kb[(kr + 4 + qq) * TST + nt * 8 + r4]);
                mma_tf32(o[nt][0], o[nt][1], o[nt][2], o[nt][3],
                         a0, a1, a2, a3, b0, b1);
            }
        }
    }

    // ---- finalize l over quad (m already quad-consistent) ----
    l0 += __shfl_xor_sync(0xffffffffu, l0, 1);
    l0 += __shfl_xor_sync(0xffffffffu, l0, 2);
    l1 += __shfl_xor_sync(0xffffffffu, l1, 1);
    l1 += __shfl_xor_sync(0xffffffffu, l1, 2);

    // ---- merge wn pair via smem (reuse ks) ----
    __syncthreads();
    float* scr = ks;                        // [4][16][TST]
    float* ml  = ks + 4 * 16 * TST;         // [64][4]
    if (wn == 1) {
        float* oa = scr + wm * 16 * TST;
#pragma unroll
        for (int nt = 0; nt < 16; nt++) {
            const int col = nt * 8 + qq * 2;
            oa[r4 * TST + col]           = o[nt][0];
            oa[r4 * TST + col + 1]       = o[nt][1];
            oa[(r4 + 8) * TST + col]     = o[nt][2];
            oa[(r4 + 8) * TST + col + 1] = o[nt][3];
        }
        if (qq == 0) {
            ml[(wm * 16 + r4) * 4]         = m0;
            ml[(wm * 16 + r4) * 4 + 1]     = l0;
            ml[(wm * 16 + r4 + 8) * 4]     = m1;
            ml[(wm * 16 + r4 + 8) * 4 + 1] = l1;
        }
    }
    __syncthreads();
    if (wn == 0) {
        float* oa = scr + wm * 16 * TST;
        float mp0 = ml[(wm * 16 + r4) * 4],     lp0 = ml[(wm * 16 + r4) * 4 + 1];
        float mp1 = ml[(wm * 16 + r4 + 8) * 4], lp1 = ml[(wm * 16 + r4 + 8) * 4 + 1];
        float mf0 = fmaxf(m0, mp0), mf1 = fmaxf(m1, mp1);
        float as0 = __expf(m0 - mf0), ap0 = __expf(mp0 - mf0);
        float as1 = __expf(m1 - mf1), ap1 = __expf(mp1 - mf1);
        float i0 = 1.f / (l0 * as0 + lp0 * ap0);
        float i1 = 1.f / (l1 * as1 + lp1 * ap1);
        const int row = q0 + wm * 16 + r4;
#pragma unroll
        for (int nt = 0; nt < 16; nt++) {
            const int col = h * DB + nt * 8 + qq * 2;
            float p00 = oa[r4 * TST + nt * 8 + qq * 2];
            float p01 = oa[r4 * TST + nt * 8 + qq * 2 + 1];
            float p10 = oa[(r4 + 8) * TST + nt * 8 + qq * 2];
            float p11 = oa[(r4 + 8) * TST + nt * 8 + qq * 2 + 1];
            float2 out0, out1;
            out0.x = (o[nt][0] * as0 + p00 * ap0) * i0;
            out0.y = (o[nt][1] * as0 + p01 * ap0) * i0;
            out1.x = (o[nt][2] * as1 + p10 * ap1) * i1;
            out1.y = (o[nt][3] * as1 + p11 * ap1) * i1;
            *(float2*)(O + (size_t)row * DD + col)       = out0;
            *(float2*)(O + (size_t)(row + 8) * DD + col) = out1;
        }
    }
}

// ============================================================================
// launch
// ============================================================================
extern "C" void kernel_launch(void* const* d_in, const int* in_sizes, int n_in,
                              void* d_out, int out_size) {
    (void)in_sizes; (void)n_in; (void)out_size;
    const float* q    = (const float*)d_in[0];
    const float* memp = (const float*)d_in[1];
    const float* w1 = (const float*)d_in[2]; const float* b1 = (const float*)d_in[3];
    const float* w2 = (const float*)d_in[4]; const float* b2 = (const float*)d_in[5];
    const float* w3 = (const float*)d_in[6]; const float* b3 = (const float*)d_in[7];
    const float* w4 = (const float*)d_in[8]; const float* b4 = (const float*)d_in[9];
    float* out = (float*)d_out;

    void *p_h1, *p_h2, *p_mem, *p_memn;
    cudaGetSymbolAddress(&p_h1, g_h1);
    cudaGetSymbolAddress(&p_h2, g_h2);
    cudaGetSymbolAddress(&p_mem, g_mem);
    cudaGetSymbolAddress(&p_memn, g_memn);
    float* h1f   = (float*)p_h1;
    float* h2f   = (float*)p_h2;
    float* memf  = (float*)p_mem;
    float* memnf = (float*)p_memn;

    // mem MLP (compensated tf32)
    gemm_tf32c<<<dim3(HH / 64, NROWS / 64), 256>>>(memp, w1, b1, h1f, NROWS, HH, DB, 1);
    gemm_tf32c<<<dim3(HH / 64, NROWS / 64), 256>>>(h1f,  w2, b2, h2f, NROWS, HH, HH, 1);
    gemm_tf32c<<<dim3(HH / 64, NROWS / 64), 256>>>(h2f,  w3, b3, h1f, NROWS, HH, HH, 1);
    gemm_tf32c<<<dim3(DB / 64, NROWS / 64), 256>>>(h1f,  w4, b4, memf, NROWS, DB, HH, 0);

    // block-LN of mem -> [h][p][d]
    mem_ln_kernel<<<NROWS / 8, 256>>>(memf, memnf);

    // flash attention (LN fused)
    const int smem_bytes = (64 * TST + 2 * 64 * TST) * sizeof(float);  // 107520
    cudaFuncSetAttribute(attn_flash, cudaFuncAttributeMaxDynamicSharedMemorySize, smem_bytes);
    attn_flash<<<dim3(QROWS / 64, NBLK), 256, smem_bytes>>>(q, memnf, out);
}

// round 8
// speedup vs baseline: 2.2176x; 1.0000x over previous
#include <cuda_runtime.h>
#include <cstdint>

// ---------------- problem dims ----------------
#define BB 8
#define NN 4096
#define DD 2048
#define NBLK 16
#define DB 128
#define PP 512
#define HH 512            // MLP hidden = 4*DB
#define NROWS (PP*NBLK)   // 8192 rows through the MLP
#define QROWS (BB*NN)     // 32768 query rows
#define EPS 1e-5f
#define INV_SQRT_DB 0.08838834764831845f

static_assert(NROWS % 64 == 0 && HH % 64 == 0 && DB % 64 == 0, "tile divisibility");
static_assert(QROWS % 64 == 0, "q tile divisibility");

// ---------------- scratch (device globals; no runtime alloc) ----------------
__device__ float g_h1[NROWS * HH];          // 16 MB
__device__ float g_h2[NROWS * HH];          // 16 MB
__device__ float g_mem[NROWS * DB];         // 4 MB
__device__ float g_memn[NBLK * PP * DB];    // 4 MB, layout [h][p][d]

// ---------------- helpers ----------------
__device__ __forceinline__ float tf32r(float x) {
    uint32_t u;
    asm("cvt.rna.tf32.f32 %0, %1;" : "=r"(u) : "f"(x));
    return __uint_as_float(u);
}
__device__ __forceinline__ uint32_t F2U(float x) { return __float_as_uint(x); }

__device__ __forceinline__ void mma_tf32(float& d0, float& d1, float& d2, float& d3,
                                         uint32_t a0, uint32_t a1, uint32_t a2, uint32_t a3,
                                         uint32_t b0, uint32_t b1) {
    asm volatile(
        "mma.sync.aligned.m16n8k8.row.col.f32.tf32.tf32.f32 "
        "{%0,%1,%2,%3}, {%4,%5,%6,%7}, {%8,%9}, {%0,%1,%2,%3};\n"
        : "+f"(d0), "+f"(d1), "+f"(d2), "+f"(d3)
        : "r"(a0), "r"(a1), "r"(a2), "r"(a3), "r"(b0), "r"(b1));
}

__device__ __forceinline__ void cp16(uint32_t saddr, const float* g) {
    asm volatile("cp.async.cg.shared.global [%0], [%1], 16;\n" :: "r"(saddr), "l"(g));
}

// ============================================================================
// GEMM: C[M,N] = act(A[M,K] @ W[N,K]^T + bias), compensated tf32 (3 MMAs)
// (unchanged from previous passing round)
// ============================================================================
#define KC 32
__global__ void __launch_bounds__(256, 2)
gemm_tf32c(const float* __restrict__ A, const float* __restrict__ W,
           const float* __restrict__ bias, float* __restrict__ C,
           int M, int N, int K, int relu) {
    __shared__ float Ah[64][KC + 4], Al[64][KC + 4];
    __shared__ float Bh[64][KC + 4], Bl[64][KC + 4];

    const int m0 = blockIdx.y * 64;
    const int n0 = blockIdx.x * 64;
    const int t = threadIdx.x;
    const int lane = t & 31;
    const int w = t >> 5;
    const int wm = w >> 1;
    const int wn = w & 1;

    float acc[4][4];
#pragma unroll
    for (int f = 0; f < 4; f++)
#pragma unroll
        for (int i = 0; i < 4; i++) acc[f][i] = 0.f;

    for (int k0 = 0; k0 < K; k0 += KC) {
        __syncthreads();
        for (int i = t; i < 64 * KC; i += 256) {
            int r = i / KC, c = i % KC;
            float va = A[(size_t)(m0 + r) * K + k0 + c];
            float vb = W[(size_t)(n0 + r) * K + k0 + c];
            float vah = tf32r(va), vbh = tf32r(vb);
            Ah[r][c] = vah;  Al[r][c] = tf32r(va - vah);
            Bh[r][c] = vbh;  Bl[r][c] = tf32r(vb - vbh);
        }
        __syncthreads();
#pragma unroll
        for (int ks = 0; ks < KC; ks += 8) {
            const int ar = wm * 16 + (lane >> 2);
            const int ac = ks + (lane & 3);
            uint32_t a0h = F2U(Ah[ar][ac]),     a1h = F2U(Ah[ar + 8][ac]);
            uint32_t a2h = F2U(Ah[ar][ac + 4]), a3h = F2U(Ah[ar + 8][ac + 4]);
            uint32_t a0l = F2U(Al[ar][ac]),     a1l = F2U(Al[ar + 8][ac]);
            uint32_t a2l = F2U(Al[ar][ac + 4]), a3l = F2U(Al[ar + 8][ac + 4]);
#pragma unroll
            for (int f = 0; f < 4; f++) {
                const int bn = wn * 32 + f * 8 + (lane >> 2);
                const int bk = ks + (lane & 3);
                uint32_t b0h = F2U(Bh[bn][bk]), b1h = F2U(Bh[bn][bk + 4]);
                uint32_t b0l = F2U(Bl[bn][bk]), b1l = F2U(Bl[bn][bk + 4]);
                mma_tf32(acc[f][0], acc[f][1], acc[f][2], acc[f][3],
                         a0h, a1h, a2h, a3h, b0h, b1h);
                mma_tf32(acc[f][0], acc[f][1], acc[f][2], acc[f][3],
                         a0h, a1h, a2h, a3h, b0l, b1l);
                mma_tf32(acc[f][0], acc[f][1], acc[f][2], acc[f][3],
                         a0l, a1l, a2l, a3l, b0h, b1h);
            }
        }
    }
    const int row = m0 + wm * 16 + (lane >> 2);
#pragma unroll
    for (int f = 0; f < 4; f++) {
        const int col = n0 + wn * 32 + f * 8 + (lane & 3) * 2;
        float bv0 = bias[col], bv1 = bias[col + 1];
        float v0 = acc[f][0] + bv0, v1 = acc[f][1] + bv1;
        float v2 = acc[f][2] + bv0, v3 = acc[f][3] + bv1;
        if (relu) {
            v0 = fmaxf(v0, 0.f); v1 = fmaxf(v1, 0.f);
            v2 = fmaxf(v2, 0.f); v3 = fmaxf(v3, 0.f);
        }
        C[(size_t)row * N + col] = v0;       C[(size_t)row * N + col + 1] = v1;
        C[(size_t)(row + 8) * N + col] = v2; C[(size_t)(row + 8) * N + col + 1] = v3;
    }
}

// ============================================================================
// Block-LN of mem rows, scatter into [h][p][d] layout (unchanged)
// ============================================================================
__global__ void __launch_bounds__(256, 4)
mem_ln_kernel(const float* __restrict__ mem, float* __restrict__ memn) {
    const int rr = blockIdx.x * 8 + (threadIdx.x >> 5);
    const int lane = threadIdx.x & 31;
    float4 v = *(const float4*)(mem + (size_t)rr * DB + lane * 4);
    float s = v.x + v.y + v.z + v.w;
    float ss = v.x * v.x + v.y * v.y + v.z * v.z + v.w * v.w;
#pragma unroll
    for (int o = 16; o; o >>= 1) {
        s  += __shfl_xor_sync(0xffffffffu, s, o);
        ss += __shfl_xor_sync(0xffffffffu, ss, o);
    }
    float mu = s * (1.f / DB);
    float var = ss * (1.f / DB) - mu * mu;
    float rs = rsqrtf(var + EPS);
    const int p = rr >> 4, h = rr & 15;
    float* o = memn + ((size_t)h * PP + p) * DB + lane * 4;
    o[0] = (v.x - mu) * rs; o[1] = (v.y - mu) * rs;
    o[2] = (v.z - mu) * rs; o[3] = (v.w - mu) * rs;
}

// ============================================================================
// Flash-style fused attention: per (q-tile 64, head).
// LN(q) -> per-warp online softmax over its 256-prototype slice, K tiles
// streamed ONCE via double-buffered cp.async, probs stay in registers
// (quad-shuffle C-frag -> A-frag), final wn-pair merge via smem.
// 256 threads, 105 KB smem, 2 CTAs/SM.
// ============================================================================
#define TST 140                 // stride (mod 32 == 12): conflict-free for
                                // qs A-frags, S-stage B-frags AND PV B-frags
#define KTILE (64 * TST)

__global__ void __launch_bounds__(256, 2)
attn_flash(const float* __restrict__ Q, const float* __restrict__ Kmem,
           float* __restrict__ O) {
    extern __shared__ float smf[];
    float* qs = smf;                 // [64][TST]
    float* ks = smf + 64 * TST;      // [2][64][TST] (reused as merge scratch)

    const int h = blockIdx.y;
    const int q0 = blockIdx.x * 64;
    const int t = threadIdx.x;
    const int lane = t & 31;
    const int w = t >> 5;
    const int wm = w >> 1, wn = w & 1;
    const int qq = lane & 3;         // quad slot
    const int r4 = lane >> 2;        // row-within-16 / n-within-8

    // ---- q block-LN (+ DB^-1/2), rna->tf32, into qs ----
    for (int rr = w; rr < 64; rr += 8) {
        const float4 v = *(const float4*)(Q + (size_t)(q0 + rr) * DD + h * DB + lane * 4);
        float s = v.x + v.y + v.z + v.w;
        float ss = v.x * v.x + v.y * v.y + v.z * v.z + v.w * v.w;
#pragma unroll
        for (int o = 16; o; o >>= 1) {
            s  += __shfl_xor_sync(0xffffffffu, s, o);
            ss += __shfl_xor_sync(0xffffffffu, ss, o);
        }
        float mu = s * (1.f / DB);
        float var = ss * (1.f / DB) - mu * mu;
        float scl = rsqrtf(var + EPS) * INV_SQRT_DB;
        float* qr = qs + rr * TST + lane * 4;
        qr[0] = tf32r((v.x - mu) * scl); qr[1] = tf32r((v.y - mu) * scl);
        qr[2] = tf32r((v.z - mu) * scl); qr[3] = tf32r((v.w - mu) * scl);
    }

    const float* KH = Kmem + (size_t)h * PP * DB;

    // prefetch K tile 0
    {
        uint32_t sb = (uint32_t)__cvta_generic_to_shared(ks);
#pragma unroll
        for (int j = 0; j < 8; j++) {
            int cid = t + j * 256;
            int r = cid >> 5, c4 = cid & 31;
            cp16(sb + (uint32_t)(r * TST + c4 * 4) * 4, KH + r * DB + c4 * 4);
        }
        asm volatile("cp.async.commit_group;\n");
    }

    float o[16][4];
#pragma unroll
    for (int nt = 0; nt < 16; nt++)
#pragma unroll
        for (int i = 0; i < 4; i++) o[nt][i] = 0.f;
    float m0 = -1e30f, m1 = -1e30f, l0 = 0.f, l1 = 0.f;

    for (int pt = 0; pt < 8; pt++) {
        asm volatile("cp.async.wait_group 0;\n");
        __syncthreads();
        const float* kb = ks + (pt & 1) * KTILE;
        if (pt < 7) {
            uint32_t sb = (uint32_t)__cvta_generic_to_shared(ks + ((pt + 1) & 1) * KTILE);
            const float* src = KH + (size_t)(pt + 1) * 64 * DB;
#pragma unroll
            for (int j = 0; j < 8; j++) {
                int cid = t + j * 256;
                int r = cid >> 5, c4 = cid & 31;
                cp16(sb + (uint32_t)(r * TST + c4 * 4) * 4, src + r * DB + c4 * 4);
            }
            asm volatile("cp.async.commit_group;\n");
        }

        // ---- S = Q @ K^T  (warp tile 16 x 32) ----
        float acc[4][4];
#pragma unroll
        for (int f = 0; f < 4; f++)
#pragma unroll
            for (int i = 0; i < 4; i++) acc[f][i] = 0.f;
        const int ar = wm * 16 + r4;
#pragma unroll
        for (int k = 0; k < DB; k += 8) {
            uint32_t a0 = F2U(qs[ar * TST + k + qq]);
            uint32_t a1 = F2U(qs[(ar + 8) * TST + k + qq]);
            uint32_t a2 = F2U(qs[ar * TST + k + 4 + qq]);
            uint32_t a3 = F2U(qs[(ar + 8) * TST + k + 4 + qq]);
#pragma unroll
            for (int f = 0; f < 4; f++) {
                const int bp = wn * 32 + f * 8 + r4;
                uint32_t b0 = F2U(kb[bp * TST + k + qq]);
                uint32_t b1 = F2U(kb[bp * TST + k + 4 + qq]);
                mma_tf32(acc[f][0], acc[f][1], acc[f][2], acc[f][3],
                         a0, a1, a2, a3, b0, b1);
            }
        }

        // ---- online softmax update (per warp, rows r4 and r4+8) ----
        float tm0 = -1e30f, tm1 = -1e30f;
#pragma unroll
        for (int f = 0; f < 4; f++) {
            tm0 = fmaxf(tm0, fmaxf(acc[f][0], acc[f][1]));
            tm1 = fmaxf(tm1, fmaxf(acc[f][2], acc[f][3]));
        }
        tm0 = fmaxf(tm0, __shfl_xor_sync(0xffffffffu, tm0, 1));
        tm0 = fmaxf(tm0, __shfl_xor_sync(0xffffffffu, tm0, 2));
        tm1 = fmaxf(tm1, __shfl_xor_sync(0xffffffffu, tm1, 1));
        tm1 = fmaxf(tm1, __shfl_xor_sync(0xffffffffu, tm1, 2));
        float mn0 = fmaxf(m0, tm0), mn1 = fmaxf(m1, tm1);
        float sc0 = __expf(m0 - mn0), sc1 = __expf(m1 - mn1);
        m0 = mn0; m1 = mn1;
        l0 *= sc0; l1 *= sc1;
#pragma unroll
        for (int nt = 0; nt < 16; nt++) {
            o[nt][0] *= sc0; o[nt][1] *= sc0;
            o[nt][2] *= sc1; o[nt][3] *= sc1;
        }
#pragma unroll
        for (int f = 0; f < 4; f++) {
            acc[f][0] = __expf(acc[f][0] - mn0);
            acc[f][1] = __expf(acc[f][1] - mn0);
            acc[f][2] = __expf(acc[f][2] - mn1);
            acc[f][3] = __expf(acc[f][3] - mn1);
            l0 += acc[f][0] + acc[f][1];
            l1 += acc[f][2] + acc[f][3];
        }

        // ---- O += P @ K  (probs reg->reg via quad shuffle) ----
        const int s0 = (lane & 28) | (qq >> 1);
        const int s1 = s0 + 2;
#pragma unroll
        for (int f = 0; f < 4; f++) {
            float v00 = __shfl_sync(0xffffffffu, acc[f][0], s0);
            float v01 = __shfl_sync(0xffffffffu, acc[f][1], s0);
            float v10 = __shfl_sync(0xffffffffu, acc[f][0], s1);
            float v11 = __shfl_sync(0xffffffffu, acc[f][1], s1);
            float w00 = __shfl_sync(0xffffffffu, acc[f][2], s0);
            float w01 = __shfl_sync(0xffffffffu, acc[f][3], s0);
            float w10 = __shfl_sync(0xffffffffu, acc[f][2], s1);
            float w11 = __shfl_sync(0xffffffffu, acc[f][3], s1);
            uint32_t a0 = F2U((qq & 1) ? v01 : v00);   // P[r4,    qq  ]
            uint32_t a2 = F2U((qq & 1) ? v11 : v10);   // P[r4,    qq+4]
            uint32_t a1 = F2U((qq & 1) ? w01 : w00);   // P[r4+8,  qq  ]
            uint32_t a3 = F2U((qq & 1) ? w11 : w10);   // P[r4+8,  qq+4]
            const int kr = wn * 32 + f * 8;
#pragma unroll
            for (int nt = 0; nt < 16; nt++) {
                uint32_t b0 = F2U(kb[(kr + qq) * TST + nt * 8 + r4]);
                uint32_t b1 = F2U(kb[(kr + 4 + qq) * TST + nt * 8 + r4]);
                mma_tf32(o[nt][0], o[nt][1], o[nt][2], o[nt][3],
                         a0, a1, a2, a3, b0, b1);
            }
        }
    }

    // ---- finalize l over quad (m already quad-consistent) ----
    l0 += __shfl_xor_sync(0xffffffffu, l0, 1);
    l0 += __shfl_xor_sync(0xffffffffu, l0, 2);
    l1 += __shfl_xor_sync(0xffffffffu, l1, 1);
    l1 += __shfl_xor_sync(0xffffffffu, l1, 2);

    // ---- merge wn pair via smem (reuse ks) ----
    __syncthreads();
    float* scr = ks;                        // [4][16][TST]
    float* ml  = ks + 4 * 16 * TST;         // [64][4]
    if (wn == 1) {
        float* oa = scr + wm * 16 * TST;
#pragma unroll
        for (int nt = 0; nt < 16; nt++) {
            const int col = nt * 8 + qq * 2;
            oa[r4 * TST + col]           = o[nt][0];
            oa[r4 * TST + col + 1]       = o[nt][1];
            oa[(r4 + 8) * TST + col]     = o[nt][2];
            oa[(r4 + 8) * TST + col + 1] = o[nt][3];
        }
        if (qq == 0) {
            ml[(wm * 16 + r4) * 4]         = m0;
            ml[(wm * 16 + r4) * 4 + 1]     = l0;
            ml[(wm * 16 + r4 + 8) * 4]     = m1;
            ml[(wm * 16 + r4 + 8) * 4 + 1] = l1;
        }
    }
    __syncthreads();
    if (wn == 0) {
        float* oa = scr + wm * 16 * TST;
        float mp0 = ml[(wm * 16 + r4) * 4],     lp0 = ml[(wm * 16 + r4) * 4 + 1];
        float mp1 = ml[(wm * 16 + r4 + 8) * 4], lp1 = ml[(wm * 16 + r4 + 8) * 4 + 1];
        float mf0 = fmaxf(m0, mp0), mf1 = fmaxf(m1, mp1);
        float as0 = __expf(m0 - mf0), ap0 = __expf(mp0 - mf0);
        float as1 = __expf(m1 - mf1), ap1 = __expf(mp1 - mf1);
        float i0 = 1.f / (l0 * as0 + lp0 * ap0);
        float i1 = 1.f / (l1 * as1 + lp1 * ap1);
        const int row = q0 + wm * 16 + r4;
#pragma unroll
        for (int nt = 0; nt < 16; nt++) {
            const int col = h * DB + nt * 8 + qq * 2;
            float p00 = oa[r4 * TST + nt * 8 + qq * 2];
            float p01 = oa[r4 * TST + nt * 8 + qq * 2 + 1];
            float p10 = oa[(r4 + 8) * TST + nt * 8 + qq * 2];
            float p11 = oa[(r4 + 8) * TST + nt * 8 + qq * 2 + 1];
            float2 out0, out1;
            out0.x = (o[nt][0] * as0 + p00 * ap0) * i0;
            out0.y = (o[nt][1] * as0 + p01 * ap0) * i0;
            out1.x = (o[nt][2] * as1 + p10 * ap1) * i1;
            out1.y = (o[nt][3] * as1 + p11 * ap1) * i1;
            *(float2*)(O + (size_t)row * DD + col)       = out0;
            *(float2*)(O + (size_t)(row + 8) * DD + col) = out1;
        }
    }
}

// ============================================================================
// launch
// ============================================================================
extern "C" void kernel_launch(void* const* d_in, const int* in_sizes, int n_in,
                              void* d_out, int out_size) {
    (void)in_sizes; (void)n_in; (void)out_size;
    const float* q    = (const float*)d_in[0];
    const float* memp = (const float*)d_in[1];
    const float* w1 = (const float*)d_in[2]; const float* b1 = (const float*)d_in[3];
    const float* w2 = (const float*)d_in[4]; const float* b2 = (const float*)d_in[5];
    const float* w3 = (const float*)d_in[6]; const float* b3 = (const float*)d_in[7];
    const float* w4 = (const float*)d_in[8]; const float* b4 = (const float*)d_in[9];
    float* out = (float*)d_out;

    void *p_h1, *p_h2, *p_mem, *p_memn;
    cudaGetSymbolAddress(&p_h1, g_h1);
    cudaGetSymbolAddress(&p_h2, g_h2);
    cudaGetSymbolAddress(&p_mem, g_mem);
    cudaGetSymbolAddress(&p_memn, g_memn);
    float* h1f   = (float*)p_h1;
    float* h2f   = (float*)p_h2;
    float* memf  = (float*)p_mem;
    float* memnf = (float*)p_memn;

    // mem MLP (compensated tf32)
    gemm_tf32c<<<dim3(HH / 64, NROWS / 64), 256>>>(memp, w1, b1, h1f, NROWS, HH, DB, 1);
    gemm_tf32c<<<dim3(HH / 64, NROWS / 64), 256>>>(h1f,  w2, b2, h2f, NROWS, HH, HH, 1);
    gemm_tf32c<<<dim3(HH / 64, NROWS / 64), 256>>>(h2f,  w3, b3, h1f, NROWS, HH, HH, 1);
    gemm_tf32c<<<dim3(DB / 64, NROWS / 64), 256>>>(h1f,  w4, b4, memf, NROWS, DB, HH, 0);

    // block-LN of mem -> [h][p][d]
    mem_ln_kernel<<<NROWS / 8, 256>>>(memf, memnf);

    // flash attention (LN fused)
    const int smem_bytes = (64 * TST + 2 * 64 * TST) * sizeof(float);  // 107520
    cudaFuncSetAttribute(attn_flash, cudaFuncAttributeMaxDynamicSharedMemorySize, smem_bytes);
    attn_flash<<<dim3(QROWS / 64, NBLK), 256, smem_bytes>>>(q, memnf, out);
}